// round 2
// baseline (speedup 1.0000x reference)
#include <cuda_runtime.h>
#include <math.h>

// SimpleLSTM: B=4096, T_HIST=60, D_IN=2, H=128, L=2, T_OUT=360
// Persistent kernel: each block owns MROWS batch rows end-to-end (no grid sync
// needed because the recurrence is independent per batch row).

#define MROWS   8
#define HDIM    128
#define GDIM    512       // 4*H
#define NTHREAD 128
#define T_HIST  60
#define T_OUT   360
#define LAYER_W_STRIDE (GDIM * HDIM)   // 65536 floats per layer

__device__ __forceinline__ float sigf(float x) {
    return 1.0f / (1.0f + expf(-x));
}

// acc[m][j] += dot(x[m][0:128], W[row_j][0:128]) for row_j = tid + 128*j
__device__ __forceinline__ void gemm_part(
    float (&acc)[MROWS][4],
    const float* __restrict__ xb,     // shared, [MROWS][128]
    const float* __restrict__ W,      // global, [512][128] row-major
    int tid)
{
    const float4* __restrict__ w0p = (const float4*)(W + (size_t)(tid      ) * HDIM);
    const float4* __restrict__ w1p = (const float4*)(W + (size_t)(tid + 128) * HDIM);
    const float4* __restrict__ w2p = (const float4*)(W + (size_t)(tid + 256) * HDIM);
    const float4* __restrict__ w3p = (const float4*)(W + (size_t)(tid + 384) * HDIM);
    const float4* __restrict__ x4  = (const float4*)xb;   // [MROWS][32]

#pragma unroll 4
    for (int k = 0; k < 32; ++k) {
        float4 w0 = w0p[k];
        float4 w1 = w1p[k];
        float4 w2 = w2p[k];
        float4 w3 = w3p[k];
#pragma unroll
        for (int m = 0; m < MROWS; ++m) {
            float4 xv = x4[m * 32 + k];
            acc[m][0] += xv.x * w0.x + xv.y * w0.y + xv.z * w0.z + xv.w * w0.w;
            acc[m][1] += xv.x * w1.x + xv.y * w1.y + xv.z * w1.z + xv.w * w1.w;
            acc[m][2] += xv.x * w2.x + xv.y * w2.y + xv.z * w2.z + xv.w * w2.w;
            acc[m][3] += xv.x * w3.x + xv.y * w3.y + xv.z * w3.z + xv.w * w3.w;
        }
    }
}

// One LSTM layer step for MROWS rows. xb: input [MROWS][128] (shared),
// hrow: h state for this layer [MROWS][128] (shared, updated in place),
// cst: c state (registers). Thread tid owns hidden unit tid (gate rows
// tid, tid+128, tid+256, tid+384 -> i,f,g,o of unit tid).
__device__ __forceinline__ void lstm_layer(
    const float* __restrict__ xb,
    float* __restrict__ hrow,
    float (&cst)[MROWS],
    const float* __restrict__ Wih,
    const float* __restrict__ Whh,
    const float (&bias)[4],
    int tid)
{
    float acc[MROWS][4];
#pragma unroll
    for (int m = 0; m < MROWS; ++m) {
#pragma unroll
        for (int j = 0; j < 4; ++j) acc[m][j] = bias[j];
    }

    gemm_part(acc, xb,   Wih, tid);
    gemm_part(acc, hrow, Whh, tid);

    __syncthreads();   // all reads of xb/hrow complete before hrow is overwritten

#pragma unroll
    for (int m = 0; m < MROWS; ++m) {
        float ig = sigf(acc[m][0]);
        float fg = sigf(acc[m][1]);
        float gg = tanhf(acc[m][2]);
        float og = sigf(acc[m][3]);
        float cn = fg * cst[m] + ig * gg;
        cst[m] = cn;
        hrow[m * HDIM + tid] = og * tanhf(cn);
    }
    __syncthreads();   // new h visible to everyone
}

__global__ __launch_bounds__(NTHREAD, 4)
void lstm_persistent_kernel(
    const float* __restrict__ history,   // (B, 60, 2)
    const float* __restrict__ emb_W,     // (128, 2)
    const float* __restrict__ emb_b,     // (128)
    const float* __restrict__ enc_Wih,   // (2, 512, 128)
    const float* __restrict__ enc_Whh,   // (2, 512, 128)
    const float* __restrict__ enc_bih,   // (2, 512)
    const float* __restrict__ enc_bhh,   // (2, 512)
    const float* __restrict__ dec_Wih,   // (2, 512, 128)
    const float* __restrict__ dec_Whh,   // (2, 512, 128)
    const float* __restrict__ dec_bih,   // (2, 512)
    const float* __restrict__ dec_bhh,   // (2, 512)
    const float* __restrict__ out_W,     // (2, 128)
    const float* __restrict__ out_b,     // (2)
    float* __restrict__ out)             // (B, 360, 2)
{
    __shared__ float h_sh[2][MROWS][HDIM];
    __shared__ float x_sh[MROWS][HDIM];
    __shared__ float pred_sh[MROWS][2];
    __shared__ float outw_sh[2][HDIM];
    __shared__ float outb_sh[2];

    const int tid = threadIdx.x;
    const int b0  = blockIdx.x * MROWS;

    // Per-thread constants (unit = tid)
    const float ew0 = emb_W[tid * 2 + 0];
    const float ew1 = emb_W[tid * 2 + 1];
    const float eb  = emb_b[tid];

    float bias_enc0[4], bias_enc1[4], bias_dec0[4], bias_dec1[4];
#pragma unroll
    for (int j = 0; j < 4; ++j) {
        int g = tid + 128 * j;
        bias_enc0[j] = enc_bih[g]       + enc_bhh[g];
        bias_enc1[j] = enc_bih[512 + g] + enc_bhh[512 + g];
        bias_dec0[j] = dec_bih[g]       + dec_bhh[g];
        bias_dec1[j] = dec_bih[512 + g] + dec_bhh[512 + g];
    }

    outw_sh[0][tid] = out_W[tid];
    outw_sh[1][tid] = out_W[128 + tid];
    if (tid < 2) outb_sh[tid] = out_b[tid];

    // Zero initial states
    float c0[MROWS], c1[MROWS];
#pragma unroll
    for (int m = 0; m < MROWS; ++m) {
        c0[m] = 0.0f;
        c1[m] = 0.0f;
        h_sh[0][m][tid] = 0.0f;
        h_sh[1][m][tid] = 0.0f;
    }
    __syncthreads();

    const float* encWih0 = enc_Wih;
    const float* encWih1 = enc_Wih + LAYER_W_STRIDE;
    const float* encWhh0 = enc_Whh;
    const float* encWhh1 = enc_Whh + LAYER_W_STRIDE;
    const float* decWih0 = dec_Wih;
    const float* decWih1 = dec_Wih + LAYER_W_STRIDE;
    const float* decWhh0 = dec_Whh;
    const float* decWhh1 = dec_Whh + LAYER_W_STRIDE;

    // ---------------- Encoder: 60 steps ----------------
    for (int t = 0; t < T_HIST; ++t) {
#pragma unroll
        for (int m = 0; m < MROWS; ++m) {
            const float* hp = history + (size_t)(b0 + m) * (T_HIST * 2) + t * 2;
            float a0 = hp[0];
            float a1 = hp[1];
            x_sh[m][tid] = a0 * ew0 + a1 * ew1 + eb;
        }
        __syncthreads();

        lstm_layer(&x_sh[0][0],    &h_sh[0][0][0], c0, encWih0, encWhh0, bias_enc0, tid);
        lstm_layer(&h_sh[0][0][0], &h_sh[1][0][0], c1, encWih1, encWhh1, bias_enc1, tid);
    }

    // ---------------- Decoder: 360 autoregressive steps ----------------
    const int wrp  = tid >> 5;
    const int lane = tid & 31;

    for (int t = 0; t < T_OUT; ++t) {
        if (t == 0) {
#pragma unroll
            for (int m = 0; m < MROWS; ++m) x_sh[m][tid] = 0.0f;
        } else {
#pragma unroll
            for (int m = 0; m < MROWS; ++m) {
                float p0 = pred_sh[m][0];
                float p1 = pred_sh[m][1];
                x_sh[m][tid] = p0 * ew0 + p1 * ew1 + eb;
            }
        }
        __syncthreads();

        lstm_layer(&x_sh[0][0],    &h_sh[0][0][0], c0, decWih0, decWhh0, bias_dec0, tid);
        lstm_layer(&h_sh[0][0][0], &h_sh[1][0][0], c1, decWih1, decWhh1, bias_dec1, tid);

        // pred = h1 @ out_W.T + out_b ; each warp handles 2 rows
#pragma unroll
        for (int mm = 0; mm < 2; ++mm) {
            int m = wrp * 2 + mm;
            float p0 = 0.0f, p1 = 0.0f;
#pragma unroll
            for (int j = 0; j < 4; ++j) {
                float hv = h_sh[1][m][lane + 32 * j];
                p0 += hv * outw_sh[0][lane + 32 * j];
                p1 += hv * outw_sh[1][lane + 32 * j];
            }
#pragma unroll
            for (int off = 16; off > 0; off >>= 1) {
                p0 += __shfl_xor_sync(0xffffffffu, p0, off);
                p1 += __shfl_xor_sync(0xffffffffu, p1, off);
            }
            if (lane == 0) {
                p0 += outb_sh[0];
                p1 += outb_sh[1];
                pred_sh[m][0] = p0;
                pred_sh[m][1] = p1;
                size_t o = (size_t)(b0 + m) * (T_OUT * 2) + (size_t)t * 2;
                out[o]     = p0;
                out[o + 1] = p1;
            }
        }
        __syncthreads();   // pred_sh ready for next step's embedding
    }
}

extern "C" void kernel_launch(void* const* d_in, const int* in_sizes, int n_in,
                              void* d_out, int out_size)
{
    const float* history = (const float*)d_in[0];
    const float* emb_W   = (const float*)d_in[1];
    const float* emb_b   = (const float*)d_in[2];
    const float* enc_Wih = (const float*)d_in[3];
    const float* enc_Whh = (const float*)d_in[4];
    const float* enc_bih = (const float*)d_in[5];
    const float* enc_bhh = (const float*)d_in[6];
    const float* dec_Wih = (const float*)d_in[7];
    const float* dec_Whh = (const float*)d_in[8];
    const float* dec_bih = (const float*)d_in[9];
    const float* dec_bhh = (const float*)d_in[10];
    const float* out_W   = (const float*)d_in[11];
    const float* out_b   = (const float*)d_in[12];
    float* out = (float*)d_out;

    const int B = 4096;
    dim3 grid(B / MROWS);
    dim3 block(NTHREAD);
    lstm_persistent_kernel<<<grid, block>>>(
        history, emb_W, emb_b,
        enc_Wih, enc_Whh, enc_bih, enc_bhh,
        dec_Wih, dec_Whh, dec_bih, dec_bhh,
        out_W, out_b, out);
}

// round 3
// speedup vs baseline: 1.4278x; 1.4278x over previous
#include <cuda_runtime.h>
#include <math.h>

// SimpleLSTM: B=4096, T_HIST=60, D_IN=2, H=128, L=2, T_OUT=360
// Persistent kernel, MROWS=16 batch rows per block, grid=256.
// Weights pre-transposed to k-major (coalesced lane access), activations
// stored k-major as batch-row pairs, compute via packed fma.rn.f32x2.

#define MROWS   16
#define NPAIR   8          // MROWS/2
#define HDIM    128
#define NTHREAD 128
#define T_HIST  60
#define T_OUT   360
#define XSTRIDE 9          // padded row stride (float2) for k-major activations

typedef unsigned long long ull;

// Transposed weights: 8 mats (encWih0,encWih1,encWhh0,encWhh1,decWih0,decWih1,
// decWhh0,decWhh1), each [64 k-pairs][512 rows] float2 = {W[row][2k2],W[row][2k2+1]}
__device__ float2 g_W2[8][64 * 512];

__device__ __forceinline__ ull ffma2(ull a, ull b, ull c) {
    ull d;
    asm("fma.rn.f32x2 %0, %1, %2, %3;" : "=l"(d) : "l"(a), "l"(b), "l"(c));
    return d;
}
__device__ __forceinline__ ull dup2(float w) {
    ull d;
    asm("mov.b64 %0, {%1, %1};" : "=l"(d) : "f"(w));
    return d;
}
__device__ __forceinline__ ull pack2(float a, float b) {
    ull d;
    asm("mov.b64 %0, {%1, %2};" : "=l"(d) : "f"(a), "f"(b));
    return d;
}
__device__ __forceinline__ void unpack2(ull v, float& a, float& b) {
    asm("mov.b64 {%0, %1}, %2;" : "=f"(a), "=f"(b) : "l"(v));
}

__device__ __forceinline__ float sigf(float x) {
    return 1.0f / (1.0f + expf(-x));
}

// ---------------- weight transpose kernel ----------------
__global__ void transpose_weights(
    const float* __restrict__ eWih, const float* __restrict__ eWhh,
    const float* __restrict__ dWih, const float* __restrict__ dWhh)
{
    int idx = blockIdx.x * 256 + threadIdx.x;   // 0 .. 8*32768-1
    int mat = idx >> 15;
    int rem = idx & 32767;
    int k2  = rem >> 9;
    int row = rem & 511;
    int grp = mat >> 1;
    int lay = mat & 1;
    const float* src =
        (grp == 0 ? eWih : grp == 1 ? eWhh : grp == 2 ? dWih : dWhh) + lay * 65536;
    float a = src[row * 128 + 2 * k2];
    float b = src[row * 128 + 2 * k2 + 1];
    g_W2[mat][k2 * 512 + row] = make_float2(a, b);
}

// ---------------- gate GEMM on batch-row pairs ----------------
// acc[p][j] (f32x2, pair p = batch rows 2p,2p+1; j = gate i/f/g/o) +=
//   sum_k x[pair][k] * W[tid+128j][k]
__device__ __forceinline__ void gemm_pairs(
    ull (&acc)[NPAIR][4],
    const float2* __restrict__ xb,      // shared, k-major [128][XSTRIDE]
    const float2* __restrict__ W2,      // global, [64][512]
    int tid)
{
#pragma unroll 2
    for (int k2 = 0; k2 < 64; ++k2) {
        float2 w0 = W2[k2 * 512 + tid];
        float2 w1 = W2[k2 * 512 + tid + 128];
        float2 w2 = W2[k2 * 512 + tid + 256];
        float2 w3 = W2[k2 * 512 + tid + 384];

        const ull* x0 = (const ull*)(xb + (2 * k2)     * XSTRIDE);
        const ull* x1 = (const ull*)(xb + (2 * k2 + 1) * XSTRIDE);
        ull xa[NPAIR], xc[NPAIR];
#pragma unroll
        for (int p = 0; p < NPAIR; ++p) { xa[p] = x0[p]; xc[p] = x1[p]; }

        ull w0x = dup2(w0.x), w0y = dup2(w0.y);
        ull w1x = dup2(w1.x), w1y = dup2(w1.y);
        ull w2x = dup2(w2.x), w2y = dup2(w2.y);
        ull w3x = dup2(w3.x), w3y = dup2(w3.y);

#pragma unroll
        for (int p = 0; p < NPAIR; ++p) {
            acc[p][0] = ffma2(w0x, xa[p], acc[p][0]);
            acc[p][1] = ffma2(w1x, xa[p], acc[p][1]);
            acc[p][2] = ffma2(w2x, xa[p], acc[p][2]);
            acc[p][3] = ffma2(w3x, xa[p], acc[p][3]);
            acc[p][0] = ffma2(w0y, xc[p], acc[p][0]);
            acc[p][1] = ffma2(w1y, xc[p], acc[p][1]);
            acc[p][2] = ffma2(w2y, xc[p], acc[p][2]);
            acc[p][3] = ffma2(w3y, xc[p], acc[p][3]);
        }
    }
}

// One LSTM layer step. xb: input activations (k-major pairs), hio: this layer's
// h state (k-major pairs, updated in place), cst: c state (scalar regs).
__device__ __forceinline__ void lstm_layer(
    const float2* __restrict__ xb,
    float2* __restrict__ hio,
    float (&cst)[MROWS],
    const float2* __restrict__ Wih2,
    const float2* __restrict__ Whh2,
    const ull (&bias)[4],
    int tid)
{
    ull acc[NPAIR][4];
#pragma unroll
    for (int p = 0; p < NPAIR; ++p)
#pragma unroll
        for (int j = 0; j < 4; ++j) acc[p][j] = bias[j];

    gemm_pairs(acc, xb,  Wih2, tid);
    gemm_pairs(acc, hio, Whh2, tid);

    __syncthreads();   // all reads of xb/hio done before hio overwrite

#pragma unroll
    for (int p = 0; p < NPAIR; ++p) {
        float i0, i1, f0, f1, g0, g1, o0, o1;
        unpack2(acc[p][0], i0, i1);
        unpack2(acc[p][1], f0, f1);
        unpack2(acc[p][2], g0, g1);
        unpack2(acc[p][3], o0, o1);
        float c0 = sigf(f0) * cst[2 * p]     + sigf(i0) * tanhf(g0);
        float c1 = sigf(f1) * cst[2 * p + 1] + sigf(i1) * tanhf(g1);
        cst[2 * p]     = c0;
        cst[2 * p + 1] = c1;
        float h0 = sigf(o0) * tanhf(c0);
        float h1 = sigf(o1) * tanhf(c1);
        *(ull*)(hio + tid * XSTRIDE + p) = pack2(h0, h1);
    }
    __syncthreads();   // new h visible to all
}

__global__ __launch_bounds__(NTHREAD, 2)
void lstm_persistent_kernel(
    const float* __restrict__ history,   // (B, 60, 2)
    const float* __restrict__ emb_W,     // (128, 2)
    const float* __restrict__ emb_b,     // (128)
    const float* __restrict__ enc_bih,   // (2, 512)
    const float* __restrict__ enc_bhh,
    const float* __restrict__ dec_bih,
    const float* __restrict__ dec_bhh,
    const float* __restrict__ out_W,     // (2, 128)
    const float* __restrict__ out_b,     // (2)
    float* __restrict__ out)             // (B, 360, 2)
{
    __shared__ float2 xp [HDIM * XSTRIDE];
    __shared__ float2 hp0[HDIM * XSTRIDE];
    __shared__ float2 hp1[HDIM * XSTRIDE];
    __shared__ float  pred_sh[MROWS][2];
    __shared__ float  outw_sh[2][HDIM];
    __shared__ float  outb_sh[2];

    const int tid = threadIdx.x;
    const int b0  = blockIdx.x * MROWS;

    const float ew0 = emb_W[tid * 2 + 0];
    const float ew1 = emb_W[tid * 2 + 1];
    const float eb  = emb_b[tid];

    ull be0[4], be1[4], bd0[4], bd1[4];
#pragma unroll
    for (int j = 0; j < 4; ++j) {
        int g = tid + 128 * j;
        float v;
        v = enc_bih[g]       + enc_bhh[g];        be0[j] = dup2(v);
        v = enc_bih[512 + g] + enc_bhh[512 + g];  be1[j] = dup2(v);
        v = dec_bih[g]       + dec_bhh[g];        bd0[j] = dup2(v);
        v = dec_bih[512 + g] + dec_bhh[512 + g];  bd1[j] = dup2(v);
    }

    outw_sh[0][tid] = out_W[tid];
    outw_sh[1][tid] = out_W[128 + tid];
    if (tid < 2) outb_sh[tid] = out_b[tid];

    float cst0[MROWS], cst1[MROWS];
#pragma unroll
    for (int m = 0; m < MROWS; ++m) { cst0[m] = 0.0f; cst1[m] = 0.0f; }
#pragma unroll
    for (int p = 0; p < NPAIR; ++p) {
        hp0[tid * XSTRIDE + p] = make_float2(0.0f, 0.0f);
        hp1[tid * XSTRIDE + p] = make_float2(0.0f, 0.0f);
    }
    __syncthreads();

    const float2* eW0 = g_W2[0];
    const float2* eW1 = g_W2[1];
    const float2* eU0 = g_W2[2];
    const float2* eU1 = g_W2[3];
    const float2* dW0 = g_W2[4];
    const float2* dW1 = g_W2[5];
    const float2* dU0 = g_W2[6];
    const float2* dU1 = g_W2[7];

    // ---------------- Encoder: 60 steps ----------------
    for (int t = 0; t < T_HIST; ++t) {
#pragma unroll
        for (int p = 0; p < NPAIR; ++p) {
            const float* h0p = history + (size_t)(b0 + 2 * p)     * (T_HIST * 2) + t * 2;
            const float* h1p = history + (size_t)(b0 + 2 * p + 1) * (T_HIST * 2) + t * 2;
            float v0 = h0p[0] * ew0 + h0p[1] * ew1 + eb;
            float v1 = h1p[0] * ew0 + h1p[1] * ew1 + eb;
            *(ull*)(xp + tid * XSTRIDE + p) = pack2(v0, v1);
        }
        __syncthreads();

        lstm_layer(xp,  hp0, cst0, eW0, eU0, be0, tid);
        lstm_layer(hp0, hp1, cst1, eW1, eU1, be1, tid);
    }

    // ---------------- Decoder: 360 autoregressive steps ----------------
    const int wrp  = tid >> 5;
    const int lane = tid & 31;

    for (int t = 0; t < T_OUT; ++t) {
        if (t == 0) {
#pragma unroll
            for (int p = 0; p < NPAIR; ++p)
                xp[tid * XSTRIDE + p] = make_float2(0.0f, 0.0f);
        } else {
#pragma unroll
            for (int p = 0; p < NPAIR; ++p) {
                float v0 = pred_sh[2 * p][0]     * ew0 + pred_sh[2 * p][1]     * ew1 + eb;
                float v1 = pred_sh[2 * p + 1][0] * ew0 + pred_sh[2 * p + 1][1] * ew1 + eb;
                *(ull*)(xp + tid * XSTRIDE + p) = pack2(v0, v1);
            }
        }
        __syncthreads();

        lstm_layer(xp,  hp0, cst0, dW0, dU0, bd0, tid);
        lstm_layer(hp0, hp1, cst1, dW1, dU1, bd1, tid);

        // pred = h1 @ out_W.T + out_b ; 4 warps x 2 pairs each
#pragma unroll
        for (int pp = 0; pp < 2; ++pp) {
            int p = wrp + 4 * pp;
            float a00 = 0.0f, a01 = 0.0f, a10 = 0.0f, a11 = 0.0f;
#pragma unroll
            for (int j = 0; j < 4; ++j) {
                int k = lane + 32 * j;
                float2 hv = hp1[k * XSTRIDE + p];
                float w0 = outw_sh[0][k];
                float w1 = outw_sh[1][k];
                a00 += hv.x * w0;  a01 += hv.x * w1;
                a10 += hv.y * w0;  a11 += hv.y * w1;
            }
#pragma unroll
            for (int off = 16; off > 0; off >>= 1) {
                a00 += __shfl_xor_sync(0xffffffffu, a00, off);
                a01 += __shfl_xor_sync(0xffffffffu, a01, off);
                a10 += __shfl_xor_sync(0xffffffffu, a10, off);
                a11 += __shfl_xor_sync(0xffffffffu, a11, off);
            }
            if (lane == 0) {
                float p00 = a00 + outb_sh[0];
                float p01 = a01 + outb_sh[1];
                float p10 = a10 + outb_sh[0];
                float p11 = a11 + outb_sh[1];
                int m0 = 2 * p, m1 = 2 * p + 1;
                pred_sh[m0][0] = p00;  pred_sh[m0][1] = p01;
                pred_sh[m1][0] = p10;  pred_sh[m1][1] = p11;
                size_t o0 = (size_t)(b0 + m0) * (T_OUT * 2) + (size_t)t * 2;
                size_t o1 = (size_t)(b0 + m1) * (T_OUT * 2) + (size_t)t * 2;
                out[o0] = p00;  out[o0 + 1] = p01;
                out[o1] = p10;  out[o1 + 1] = p11;
            }
        }
        __syncthreads();   // pred_sh stable for next step
    }
}

extern "C" void kernel_launch(void* const* d_in, const int* in_sizes, int n_in,
                              void* d_out, int out_size)
{
    const float* history = (const float*)d_in[0];
    const float* emb_W   = (const float*)d_in[1];
    const float* emb_b   = (const float*)d_in[2];
    const float* enc_Wih = (const float*)d_in[3];
    const float* enc_Whh = (const float*)d_in[4];
    const float* enc_bih = (const float*)d_in[5];
    const float* enc_bhh = (const float*)d_in[6];
    const float* dec_Wih = (const float*)d_in[7];
    const float* dec_Whh = (const float*)d_in[8];
    const float* dec_bih = (const float*)d_in[9];
    const float* dec_bhh = (const float*)d_in[10];
    const float* out_W   = (const float*)d_in[11];
    const float* out_b   = (const float*)d_in[12];
    float* out = (float*)d_out;

    transpose_weights<<<1024, 256>>>(enc_Wih, enc_Whh, dec_Wih, dec_Whh);

    const int B = 4096;
    lstm_persistent_kernel<<<B / MROWS, NTHREAD>>>(
        history, emb_W, emb_b,
        enc_bih, enc_bhh, dec_bih, dec_bhh,
        out_W, out_b, out);
}

// round 4
// speedup vs baseline: 2.5996x; 1.8207x over previous
#include <cuda_runtime.h>
#include <math.h>

// SimpleLSTM: B=4096, T_HIST=60, D_IN=2, H=128, L=2, T_OUT=360
// Persistent kernel, MROWS=16 batch rows per block, grid=256.
// Weights pre-transposed to k-major (coalesced lane access), activations
// stored k-major as batch-row pairs, compute via packed fma.rn.f32x2.

#define MROWS   16
#define NPAIR   8          // MROWS/2
#define HDIM    128
#define NTHREAD 128
#define T_HIST  60
#define T_OUT   360
#define XSTRIDE 9          // padded row stride (float2) for k-major activations

typedef unsigned long long ull;

// Transposed weights: 8 mats (encWih0,encWih1,encWhh0,encWhh1,decWih0,decWih1,
// decWhh0,decWhh1), each [64 k-pairs][512 rows] float2 = {W[row][2k2],W[row][2k2+1]}
__device__ float2 g_W2[8][64 * 512];

__device__ __forceinline__ ull ffma2(ull a, ull b, ull c) {
    ull d;
    asm("fma.rn.f32x2 %0, %1, %2, %3;" : "=l"(d) : "l"(a), "l"(b), "l"(c));
    return d;
}
__device__ __forceinline__ ull dup2(float w) {
    ull d;
    asm("mov.b64 %0, {%1, %1};" : "=l"(d) : "f"(w));
    return d;
}
__device__ __forceinline__ ull pack2(float a, float b) {
    ull d;
    asm("mov.b64 %0, {%1, %2};" : "=l"(d) : "f"(a), "f"(b));
    return d;
}
__device__ __forceinline__ void unpack2(ull v, float& a, float& b) {
    asm("mov.b64 {%0, %1}, %2;" : "=f"(a), "=f"(b) : "l"(v));
}

__device__ __forceinline__ float sigf(float x) {
    return 1.0f / (1.0f + expf(-x));
}

// ---------------- weight transpose kernel ----------------
__global__ void transpose_weights(
    const float* __restrict__ eWih, const float* __restrict__ eWhh,
    const float* __restrict__ dWih, const float* __restrict__ dWhh)
{
    int idx = blockIdx.x * 256 + threadIdx.x;   // 0 .. 8*32768-1
    int mat = idx >> 15;
    int rem = idx & 32767;
    int k2  = rem >> 9;
    int row = rem & 511;
    int grp = mat >> 1;
    int lay = mat & 1;
    const float* src =
        (grp == 0 ? eWih : grp == 1 ? eWhh : grp == 2 ? dWih : dWhh) + lay * 65536;
    float a = src[row * 128 + 2 * k2];
    float b = src[row * 128 + 2 * k2 + 1];
    g_W2[mat][k2 * 512 + row] = make_float2(a, b);
}

// ---------------- gate GEMM on batch-row pairs ----------------
// acc[p][j] (f32x2, pair p = batch rows 2p,2p+1; j = gate i/f/g/o) +=
//   sum_k x[pair][k] * W[tid+128j][k]
__device__ __forceinline__ void gemm_pairs(
    ull (&acc)[NPAIR][4],
    const float2* __restrict__ xb,      // shared, k-major [128][XSTRIDE]
    const float2* __restrict__ W2,      // global, [64][512]
    int tid)
{
#pragma unroll 2
    for (int k2 = 0; k2 < 64; ++k2) {
        float2 w0 = W2[k2 * 512 + tid];
        float2 w1 = W2[k2 * 512 + tid + 128];
        float2 w2 = W2[k2 * 512 + tid + 256];
        float2 w3 = W2[k2 * 512 + tid + 384];

        const ull* x0 = (const ull*)(xb + (2 * k2)     * XSTRIDE);
        const ull* x1 = (const ull*)(xb + (2 * k2 + 1) * XSTRIDE);
        ull xa[NPAIR], xc[NPAIR];
#pragma unroll
        for (int p = 0; p < NPAIR; ++p) { xa[p] = x0[p]; xc[p] = x1[p]; }

        ull w0x = dup2(w0.x), w0y = dup2(w0.y);
        ull w1x = dup2(w1.x), w1y = dup2(w1.y);
        ull w2x = dup2(w2.x), w2y = dup2(w2.y);
        ull w3x = dup2(w3.x), w3y = dup2(w3.y);

#pragma unroll
        for (int p = 0; p < NPAIR; ++p) {
            acc[p][0] = ffma2(w0x, xa[p], acc[p][0]);
            acc[p][1] = ffma2(w1x, xa[p], acc[p][1]);
            acc[p][2] = ffma2(w2x, xa[p], acc[p][2]);
            acc[p][3] = ffma2(w3x, xa[p], acc[p][3]);
            acc[p][0] = ffma2(w0y, xc[p], acc[p][0]);
            acc[p][1] = ffma2(w1y, xc[p], acc[p][1]);
            acc[p][2] = ffma2(w2y, xc[p], acc[p][2]);
            acc[p][3] = ffma2(w3y, xc[p], acc[p][3]);
        }
    }
}

// One LSTM layer step. xb: input activations (k-major pairs), hio: this layer's
// h state (k-major pairs, updated in place), cst: c state (scalar regs).
__device__ __forceinline__ void lstm_layer(
    const float2* __restrict__ xb,
    float2* __restrict__ hio,
    float (&cst)[MROWS],
    const float2* __restrict__ Wih2,
    const float2* __restrict__ Whh2,
    const ull (&bias)[4],
    int tid)
{
    ull acc[NPAIR][4];
#pragma unroll
    for (int p = 0; p < NPAIR; ++p)
#pragma unroll
        for (int j = 0; j < 4; ++j) acc[p][j] = bias[j];

    gemm_pairs(acc, xb,  Wih2, tid);
    gemm_pairs(acc, hio, Whh2, tid);

    __syncthreads();   // all reads of xb/hio done before hio overwrite

#pragma unroll
    for (int p = 0; p < NPAIR; ++p) {
        float i0, i1, f0, f1, g0, g1, o0, o1;
        unpack2(acc[p][0], i0, i1);
        unpack2(acc[p][1], f0, f1);
        unpack2(acc[p][2], g0, g1);
        unpack2(acc[p][3], o0, o1);
        float c0 = sigf(f0) * cst[2 * p]     + sigf(i0) * tanhf(g0);
        float c1 = sigf(f1) * cst[2 * p + 1] + sigf(i1) * tanhf(g1);
        cst[2 * p]     = c0;
        cst[2 * p + 1] = c1;
        float h0 = sigf(o0) * tanhf(c0);
        float h1 = sigf(o1) * tanhf(c1);
        *(ull*)(hio + tid * XSTRIDE + p) = pack2(h0, h1);
    }
    __syncthreads();   // new h visible to all
}

__global__ __launch_bounds__(NTHREAD, 2)
void lstm_persistent_kernel(
    const float* __restrict__ history,   // (B, 60, 2)
    const float* __restrict__ emb_W,     // (128, 2)
    const float* __restrict__ emb_b,     // (128)
    const float* __restrict__ enc_bih,   // (2, 512)
    const float* __restrict__ enc_bhh,
    const float* __restrict__ dec_bih,
    const float* __restrict__ dec_bhh,
    const float* __restrict__ out_W,     // (2, 128)
    const float* __restrict__ out_b,     // (2)
    float* __restrict__ out)             // (B, 360, 2)
{
    __shared__ float2 xp [HDIM * XSTRIDE];
    __shared__ float2 hp0[HDIM * XSTRIDE];
    __shared__ float2 hp1[HDIM * XSTRIDE];
    __shared__ float  pred_sh[MROWS][2];
    __shared__ float  outw_sh[2][HDIM];
    __shared__ float  outb_sh[2];

    const int tid = threadIdx.x;
    const int b0  = blockIdx.x * MROWS;

    const float ew0 = emb_W[tid * 2 + 0];
    const float ew1 = emb_W[tid * 2 + 1];
    const float eb  = emb_b[tid];

    ull be0[4], be1[4], bd0[4], bd1[4];
#pragma unroll
    for (int j = 0; j < 4; ++j) {
        int g = tid + 128 * j;
        float v;
        v = enc_bih[g]       + enc_bhh[g];        be0[j] = dup2(v);
        v = enc_bih[512 + g] + enc_bhh[512 + g];  be1[j] = dup2(v);
        v = dec_bih[g]       + dec_bhh[g];        bd0[j] = dup2(v);
        v = dec_bih[512 + g] + dec_bhh[512 + g];  bd1[j] = dup2(v);
    }

    outw_sh[0][tid] = out_W[tid];
    outw_sh[1][tid] = out_W[128 + tid];
    if (tid < 2) outb_sh[tid] = out_b[tid];

    float cst0[MROWS], cst1[MROWS];
#pragma unroll
    for (int m = 0; m < MROWS; ++m) { cst0[m] = 0.0f; cst1[m] = 0.0f; }
#pragma unroll
    for (int p = 0; p < NPAIR; ++p) {
        hp0[tid * XSTRIDE + p] = make_float2(0.0f, 0.0f);
        hp1[tid * XSTRIDE + p] = make_float2(0.0f, 0.0f);
    }
    __syncthreads();

    const float2* eW0 = g_W2[0];
    const float2* eW1 = g_W2[1];
    const float2* eU0 = g_W2[2];
    const float2* eU1 = g_W2[3];
    const float2* dW0 = g_W2[4];
    const float2* dW1 = g_W2[5];
    const float2* dU0 = g_W2[6];
    const float2* dU1 = g_W2[7];

    // ---------------- Encoder: 60 steps ----------------
    for (int t = 0; t < T_HIST; ++t) {
#pragma unroll
        for (int p = 0; p < NPAIR; ++p) {
            const float* h0p = history + (size_t)(b0 + 2 * p)     * (T_HIST * 2) + t * 2;
            const float* h1p = history + (size_t)(b0 + 2 * p + 1) * (T_HIST * 2) + t * 2;
            float v0 = h0p[0] * ew0 + h0p[1] * ew1 + eb;
            float v1 = h1p[0] * ew0 + h1p[1] * ew1 + eb;
            *(ull*)(xp + tid * XSTRIDE + p) = pack2(v0, v1);
        }
        __syncthreads();

        lstm_layer(xp,  hp0, cst0, eW0, eU0, be0, tid);
        lstm_layer(hp0, hp1, cst1, eW1, eU1, be1, tid);
    }

    // ---------------- Decoder: 360 autoregressive steps ----------------
    const int wrp  = tid >> 5;
    const int lane = tid & 31;

    for (int t = 0; t < T_OUT; ++t) {
        if (t == 0) {
#pragma unroll
            for (int p = 0; p < NPAIR; ++p)
                xp[tid * XSTRIDE + p] = make_float2(0.0f, 0.0f);
        } else {
#pragma unroll
            for (int p = 0; p < NPAIR; ++p) {
                float v0 = pred_sh[2 * p][0]     * ew0 + pred_sh[2 * p][1]     * ew1 + eb;
                float v1 = pred_sh[2 * p + 1][0] * ew0 + pred_sh[2 * p + 1][1] * ew1 + eb;
                *(ull*)(xp + tid * XSTRIDE + p) = pack2(v0, v1);
            }
        }
        __syncthreads();

        lstm_layer(xp,  hp0, cst0, dW0, dU0, bd0, tid);
        lstm_layer(hp0, hp1, cst1, dW1, dU1, bd1, tid);

        // pred = h1 @ out_W.T + out_b ; 4 warps x 2 pairs each
#pragma unroll
        for (int pp = 0; pp < 2; ++pp) {
            int p = wrp + 4 * pp;
            float a00 = 0.0f, a01 = 0.0f, a10 = 0.0f, a11 = 0.0f;
#pragma unroll
            for (int j = 0; j < 4; ++j) {
                int k = lane + 32 * j;
                float2 hv = hp1[k * XSTRIDE + p];
                float w0 = outw_sh[0][k];
                float w1 = outw_sh[1][k];
                a00 += hv.x * w0;  a01 += hv.x * w1;
                a10 += hv.y * w0;  a11 += hv.y * w1;
            }
#pragma unroll
            for (int off = 16; off > 0; off >>= 1) {
                a00 += __shfl_xor_sync(0xffffffffu, a00, off);
                a01 += __shfl_xor_sync(0xffffffffu, a01, off);
                a10 += __shfl_xor_sync(0xffffffffu, a10, off);
                a11 += __shfl_xor_sync(0xffffffffu, a11, off);
            }
            if (lane == 0) {
                float p00 = a00 + outb_sh[0];
                float p01 = a01 + outb_sh[1];
                float p10 = a10 + outb_sh[0];
                float p11 = a11 + outb_sh[1];
                int m0 = 2 * p, m1 = 2 * p + 1;
                pred_sh[m0][0] = p00;  pred_sh[m0][1] = p01;
                pred_sh[m1][0] = p10;  pred_sh[m1][1] = p11;
                size_t o0 = (size_t)(b0 + m0) * (T_OUT * 2) + (size_t)t * 2;
                size_t o1 = (size_t)(b0 + m1) * (T_OUT * 2) + (size_t)t * 2;
                out[o0] = p00;  out[o0 + 1] = p01;
                out[o1] = p10;  out[o1 + 1] = p11;
            }
        }
        __syncthreads();   // pred_sh stable for next step
    }
}

extern "C" void kernel_launch(void* const* d_in, const int* in_sizes, int n_in,
                              void* d_out, int out_size)
{
    const float* history = (const float*)d_in[0];
    const float* emb_W   = (const float*)d_in[1];
    const float* emb_b   = (const float*)d_in[2];
    const float* enc_Wih = (const float*)d_in[3];
    const float* enc_Whh = (const float*)d_in[4];
    const float* enc_bih = (const float*)d_in[5];
    const float* enc_bhh = (const float*)d_in[6];
    const float* dec_Wih = (const float*)d_in[7];
    const float* dec_Whh = (const float*)d_in[8];
    const float* dec_bih = (const float*)d_in[9];
    const float* dec_bhh = (const float*)d_in[10];
    const float* out_W   = (const float*)d_in[11];
    const float* out_b   = (const float*)d_in[12];
    float* out = (float*)d_out;

    transpose_weights<<<1024, 256>>>(enc_Wih, enc_Whh, dec_Wih, dec_Whh);

    const int B = 4096;
    lstm_persistent_kernel<<<B / MROWS, NTHREAD>>>(
        history, emb_W, emb_b,
        enc_bih, enc_bhh, dec_bih, dec_bhh,
        out_W, out_b, out);
}

// round 5
// speedup vs baseline: 2.6133x; 1.0053x over previous
#include <cuda_runtime.h>
#include <math.h>

// SimpleLSTM: B=4096, T_HIST=60, D_IN=2, H=128, L=2, T_OUT=360
// Persistent kernel, MROWS=16 batch rows per block, grid=256.
// Weights pre-transposed to k-major (coalesced lane access), activations
// stored k-major as batch-row pairs, compute via packed fma.rn.f32x2.

#define MROWS   16
#define NPAIR   8          // MROWS/2
#define HDIM    128
#define NTHREAD 128
#define T_HIST  60
#define T_OUT   360
#define XSTRIDE 9          // padded row stride (float2) for k-major activations

typedef unsigned long long ull;

// Transposed weights: 8 mats (encWih0,encWih1,encWhh0,encWhh1,decWih0,decWih1,
// decWhh0,decWhh1), each [64 k-pairs][512 rows] float2 = {W[row][2k2],W[row][2k2+1]}
__device__ float2 g_W2[8][64 * 512];

__device__ __forceinline__ ull ffma2(ull a, ull b, ull c) {
    ull d;
    asm("fma.rn.f32x2 %0, %1, %2, %3;" : "=l"(d) : "l"(a), "l"(b), "l"(c));
    return d;
}
__device__ __forceinline__ ull dup2(float w) {
    ull d;
    asm("mov.b64 %0, {%1, %1};" : "=l"(d) : "f"(w));
    return d;
}
__device__ __forceinline__ ull pack2(float a, float b) {
    ull d;
    asm("mov.b64 %0, {%1, %2};" : "=l"(d) : "f"(a), "f"(b));
    return d;
}
__device__ __forceinline__ void unpack2(ull v, float& a, float& b) {
    asm("mov.b64 {%0, %1}, %2;" : "=f"(a), "=f"(b) : "l"(v));
}

__device__ __forceinline__ float sigf(float x) {
    return 1.0f / (1.0f + expf(-x));
}

// ---------------- weight transpose kernel ----------------
__global__ void transpose_weights(
    const float* __restrict__ eWih, const float* __restrict__ eWhh,
    const float* __restrict__ dWih, const float* __restrict__ dWhh)
{
    int idx = blockIdx.x * 256 + threadIdx.x;   // 0 .. 8*32768-1
    int mat = idx >> 15;
    int rem = idx & 32767;
    int k2  = rem >> 9;
    int row = rem & 511;
    int grp = mat >> 1;
    int lay = mat & 1;
    const float* src =
        (grp == 0 ? eWih : grp == 1 ? eWhh : grp == 2 ? dWih : dWhh) + lay * 65536;
    float a = src[row * 128 + 2 * k2];
    float b = src[row * 128 + 2 * k2 + 1];
    g_W2[mat][k2 * 512 + row] = make_float2(a, b);
}

// ---------------- gate GEMM on batch-row pairs ----------------
// acc[p][j] (f32x2, pair p = batch rows 2p,2p+1; j = gate i/f/g/o) +=
//   sum_k x[pair][k] * W[tid+128j][k]
__device__ __forceinline__ void gemm_pairs(
    ull (&acc)[NPAIR][4],
    const float2* __restrict__ xb,      // shared, k-major [128][XSTRIDE]
    const float2* __restrict__ W2,      // global, [64][512]
    int tid)
{
#pragma unroll 2
    for (int k2 = 0; k2 < 64; ++k2) {
        float2 w0 = W2[k2 * 512 + tid];
        float2 w1 = W2[k2 * 512 + tid + 128];
        float2 w2 = W2[k2 * 512 + tid + 256];
        float2 w3 = W2[k2 * 512 + tid + 384];

        const ull* x0 = (const ull*)(xb + (2 * k2)     * XSTRIDE);
        const ull* x1 = (const ull*)(xb + (2 * k2 + 1) * XSTRIDE);
        ull xa[NPAIR], xc[NPAIR];
#pragma unroll
        for (int p = 0; p < NPAIR; ++p) { xa[p] = x0[p]; xc[p] = x1[p]; }

        ull w0x = dup2(w0.x), w0y = dup2(w0.y);
        ull w1x = dup2(w1.x), w1y = dup2(w1.y);
        ull w2x = dup2(w2.x), w2y = dup2(w2.y);
        ull w3x = dup2(w3.x), w3y = dup2(w3.y);

#pragma unroll
        for (int p = 0; p < NPAIR; ++p) {
            acc[p][0] = ffma2(w0x, xa[p], acc[p][0]);
            acc[p][1] = ffma2(w1x, xa[p], acc[p][1]);
            acc[p][2] = ffma2(w2x, xa[p], acc[p][2]);
            acc[p][3] = ffma2(w3x, xa[p], acc[p][3]);
            acc[p][0] = ffma2(w0y, xc[p], acc[p][0]);
            acc[p][1] = ffma2(w1y, xc[p], acc[p][1]);
            acc[p][2] = ffma2(w2y, xc[p], acc[p][2]);
            acc[p][3] = ffma2(w3y, xc[p], acc[p][3]);
        }
    }
}

// One LSTM layer step. xb: input activations (k-major pairs), hio: this layer's
// h state (k-major pairs, updated in place), cst: c state (scalar regs).
__device__ __forceinline__ void lstm_layer(
    const float2* __restrict__ xb,
    float2* __restrict__ hio,
    float (&cst)[MROWS],
    const float2* __restrict__ Wih2,
    const float2* __restrict__ Whh2,
    const ull (&bias)[4],
    int tid)
{
    ull acc[NPAIR][4];
#pragma unroll
    for (int p = 0; p < NPAIR; ++p)
#pragma unroll
        for (int j = 0; j < 4; ++j) acc[p][j] = bias[j];

    gemm_pairs(acc, xb,  Wih2, tid);
    gemm_pairs(acc, hio, Whh2, tid);

    __syncthreads();   // all reads of xb/hio done before hio overwrite

#pragma unroll
    for (int p = 0; p < NPAIR; ++p) {
        float i0, i1, f0, f1, g0, g1, o0, o1;
        unpack2(acc[p][0], i0, i1);
        unpack2(acc[p][1], f0, f1);
        unpack2(acc[p][2], g0, g1);
        unpack2(acc[p][3], o0, o1);
        float c0 = sigf(f0) * cst[2 * p]     + sigf(i0) * tanhf(g0);
        float c1 = sigf(f1) * cst[2 * p + 1] + sigf(i1) * tanhf(g1);
        cst[2 * p]     = c0;
        cst[2 * p + 1] = c1;
        float h0 = sigf(o0) * tanhf(c0);
        float h1 = sigf(o1) * tanhf(c1);
        *(ull*)(hio + tid * XSTRIDE + p) = pack2(h0, h1);
    }
    __syncthreads();   // new h visible to all
}

__global__ __launch_bounds__(NTHREAD, 2)
void lstm_persistent_kernel(
    const float* __restrict__ history,   // (B, 60, 2)
    const float* __restrict__ emb_W,     // (128, 2)
    const float* __restrict__ emb_b,     // (128)
    const float* __restrict__ enc_bih,   // (2, 512)
    const float* __restrict__ enc_bhh,
    const float* __restrict__ dec_bih,
    const float* __restrict__ dec_bhh,
    const float* __restrict__ out_W,     // (2, 128)
    const float* __restrict__ out_b,     // (2)
    float* __restrict__ out)             // (B, 360, 2)
{
    __shared__ float2 xp [HDIM * XSTRIDE];
    __shared__ float2 hp0[HDIM * XSTRIDE];
    __shared__ float2 hp1[HDIM * XSTRIDE];
    __shared__ float  pred_sh[MROWS][2];
    __shared__ float  outw_sh[2][HDIM];
    __shared__ float  outb_sh[2];

    const int tid = threadIdx.x;
    const int b0  = blockIdx.x * MROWS;

    const float ew0 = emb_W[tid * 2 + 0];
    const float ew1 = emb_W[tid * 2 + 1];
    const float eb  = emb_b[tid];

    ull be0[4], be1[4], bd0[4], bd1[4];
#pragma unroll
    for (int j = 0; j < 4; ++j) {
        int g = tid + 128 * j;
        float v;
        v = enc_bih[g]       + enc_bhh[g];        be0[j] = dup2(v);
        v = enc_bih[512 + g] + enc_bhh[512 + g];  be1[j] = dup2(v);
        v = dec_bih[g]       + dec_bhh[g];        bd0[j] = dup2(v);
        v = dec_bih[512 + g] + dec_bhh[512 + g];  bd1[j] = dup2(v);
    }

    outw_sh[0][tid] = out_W[tid];
    outw_sh[1][tid] = out_W[128 + tid];
    if (tid < 2) outb_sh[tid] = out_b[tid];

    float cst0[MROWS], cst1[MROWS];
#pragma unroll
    for (int m = 0; m < MROWS; ++m) { cst0[m] = 0.0f; cst1[m] = 0.0f; }
#pragma unroll
    for (int p = 0; p < NPAIR; ++p) {
        hp0[tid * XSTRIDE + p] = make_float2(0.0f, 0.0f);
        hp1[tid * XSTRIDE + p] = make_float2(0.0f, 0.0f);
    }
    __syncthreads();

    const float2* eW0 = g_W2[0];
    const float2* eW1 = g_W2[1];
    const float2* eU0 = g_W2[2];
    const float2* eU1 = g_W2[3];
    const float2* dW0 = g_W2[4];
    const float2* dW1 = g_W2[5];
    const float2* dU0 = g_W2[6];
    const float2* dU1 = g_W2[7];

    // ---------------- Encoder: 60 steps ----------------
    for (int t = 0; t < T_HIST; ++t) {
#pragma unroll
        for (int p = 0; p < NPAIR; ++p) {
            const float* h0p = history + (size_t)(b0 + 2 * p)     * (T_HIST * 2) + t * 2;
            const float* h1p = history + (size_t)(b0 + 2 * p + 1) * (T_HIST * 2) + t * 2;
            float v0 = h0p[0] * ew0 + h0p[1] * ew1 + eb;
            float v1 = h1p[0] * ew0 + h1p[1] * ew1 + eb;
            *(ull*)(xp + tid * XSTRIDE + p) = pack2(v0, v1);
        }
        __syncthreads();

        lstm_layer(xp,  hp0, cst0, eW0, eU0, be0, tid);
        lstm_layer(hp0, hp1, cst1, eW1, eU1, be1, tid);
    }

    // ---------------- Decoder: 360 autoregressive steps ----------------
    const int wrp  = tid >> 5;
    const int lane = tid & 31;

    for (int t = 0; t < T_OUT; ++t) {
        if (t == 0) {
#pragma unroll
            for (int p = 0; p < NPAIR; ++p)
                xp[tid * XSTRIDE + p] = make_float2(0.0f, 0.0f);
        } else {
#pragma unroll
            for (int p = 0; p < NPAIR; ++p) {
                float v0 = pred_sh[2 * p][0]     * ew0 + pred_sh[2 * p][1]     * ew1 + eb;
                float v1 = pred_sh[2 * p + 1][0] * ew0 + pred_sh[2 * p + 1][1] * ew1 + eb;
                *(ull*)(xp + tid * XSTRIDE + p) = pack2(v0, v1);
            }
        }
        __syncthreads();

        lstm_layer(xp,  hp0, cst0, dW0, dU0, bd0, tid);
        lstm_layer(hp0, hp1, cst1, dW1, dU1, bd1, tid);

        // pred = h1 @ out_W.T + out_b ; 4 warps x 2 pairs each
#pragma unroll
        for (int pp = 0; pp < 2; ++pp) {
            int p = wrp + 4 * pp;
            float a00 = 0.0f, a01 = 0.0f, a10 = 0.0f, a11 = 0.0f;
#pragma unroll
            for (int j = 0; j < 4; ++j) {
                int k = lane + 32 * j;
                float2 hv = hp1[k * XSTRIDE + p];
                float w0 = outw_sh[0][k];
                float w1 = outw_sh[1][k];
                a00 += hv.x * w0;  a01 += hv.x * w1;
                a10 += hv.y * w0;  a11 += hv.y * w1;
            }
#pragma unroll
            for (int off = 16; off > 0; off >>= 1) {
                a00 += __shfl_xor_sync(0xffffffffu, a00, off);
                a01 += __shfl_xor_sync(0xffffffffu, a01, off);
                a10 += __shfl_xor_sync(0xffffffffu, a10, off);
                a11 += __shfl_xor_sync(0xffffffffu, a11, off);
            }
            if (lane == 0) {
                float p00 = a00 + outb_sh[0];
                float p01 = a01 + outb_sh[1];
                float p10 = a10 + outb_sh[0];
                float p11 = a11 + outb_sh[1];
                int m0 = 2 * p, m1 = 2 * p + 1;
                pred_sh[m0][0] = p00;  pred_sh[m0][1] = p01;
                pred_sh[m1][0] = p10;  pred_sh[m1][1] = p11;
                size_t o0 = (size_t)(b0 + m0) * (T_OUT * 2) + (size_t)t * 2;
                size_t o1 = (size_t)(b0 + m1) * (T_OUT * 2) + (size_t)t * 2;
                out[o0] = p00;  out[o0 + 1] = p01;
                out[o1] = p10;  out[o1 + 1] = p11;
            }
        }
        __syncthreads();   // pred_sh stable for next step
    }
}

extern "C" void kernel_launch(void* const* d_in, const int* in_sizes, int n_in,
                              void* d_out, int out_size)
{
    const float* history = (const float*)d_in[0];
    const float* emb_W   = (const float*)d_in[1];
    const float* emb_b   = (const float*)d_in[2];
    const float* enc_Wih = (const float*)d_in[3];
    const float* enc_Whh = (const float*)d_in[4];
    const float* enc_bih = (const float*)d_in[5];
    const float* enc_bhh = (const float*)d_in[6];
    const float* dec_Wih = (const float*)d_in[7];
    const float* dec_Whh = (const float*)d_in[8];
    const float* dec_bih = (const float*)d_in[9];
    const float* dec_bhh = (const float*)d_in[10];
    const float* out_W   = (const float*)d_in[11];
    const float* out_b   = (const float*)d_in[12];
    float* out = (float*)d_out;

    transpose_weights<<<1024, 256>>>(enc_Wih, enc_Whh, dec_Wih, dec_Whh);

    const int B = 4096;
    lstm_persistent_kernel<<<B / MROWS, NTHREAD>>>(
        history, emb_W, emb_b,
        enc_bih, enc_bhh, dec_bih, dec_bhh,
        out_W, out_b, out);
}